// round 1
// baseline (speedup 1.0000x reference)
#include <cuda_runtime.h>

// ---------------------------------------------------------------------------
// MultiHeadSelfAttention: B=128,H=128,F=8,D=200, nh=10, hd=20
// x flat: (131072, 200). Q=XWq, K=XWk, V=XWv (each 131072x200).
// Per (i in 1024, h in 10): rows i*128..i*128+127, cols h*20..h*20+19.
// scores = qk^T/sqrt(20); softmax; attn -> d_out[0:167772160]
// ctx = attn @ v  (flat 131072x200); out = ctx @ Wq -> d_out[167772160:]
// ---------------------------------------------------------------------------

#define M_ROWS 131072L
#define DPAD 201            // x-tile row pitch (odd -> conflict-free broadcasts)

__device__ float g_q[131072L * 200];
__device__ float g_k[131072L * 200];
__device__ float g_v[131072L * 200];
__device__ float g_ctx[131072L * 200];

// ------------------------ SGEMM: (M x 200) @ (200 x 200) -------------------
// Full W resident in smem (160KB). 80-row A tile. 512 threads:
// thread = (rg in 0..9, cg in 0..49); micro-tile 8 rows x 4 cols (float4 of W).
__global__ __launch_bounds__(512, 1)
void sgemm200(const float* __restrict__ A, const float* __restrict__ B,
              float* __restrict__ C) {
    extern __shared__ float sm[];
    float* ws = sm;                 // 200*200 = 40000 floats
    float* xs = sm + 40000;         // 80 * DPAD floats
    const int tid = threadIdx.x;

    // Load W (40000 floats = 10000 float4), coalesced.
    {
        const float4* B4 = (const float4*)B;
        float4* ws4 = (float4*)ws;
        #pragma unroll
        for (int i0 = 0; i0 < 20; i0++) {
            int idx = tid + i0 * 512;
            if (idx < 10000) ws4[idx] = B4[idx];
        }
    }
    // Load A tile (80 x 200) into padded smem, coalesced scalar loads.
    const long row0 = (long)blockIdx.x * 80;
    long rem = M_ROWS - row0;
    const int rows = rem < 80 ? (int)rem : 80;
    {
        const float* Ab = A + row0 * 200;
        for (int i = tid; i < 16000; i += 512) {
            int r = i / 200;
            int c = i - r * 200;
            if (r < rows) xs[r * DPAD + c] = Ab[i];
        }
    }
    __syncthreads();

    const int cg = tid % 50;
    const int rg = tid / 50;
    if (rg < 10) {
        float acc[8][4];
        #pragma unroll
        for (int rr = 0; rr < 8; rr++) {
            acc[rr][0] = 0.f; acc[rr][1] = 0.f; acc[rr][2] = 0.f; acc[rr][3] = 0.f;
        }
        const float* xb = xs + rg * 8 * DPAD;
        const float4* wc = (const float4*)ws + cg;   // column-quad of W
        #pragma unroll 2
        for (int k = 0; k < 200; k++) {
            float4 w = wc[k * 50];
            #pragma unroll
            for (int rr = 0; rr < 8; rr++) {
                float xv = xb[rr * DPAD + k];        // broadcast within warp
                acc[rr][0] += xv * w.x;
                acc[rr][1] += xv * w.y;
                acc[rr][2] += xv * w.z;
                acc[rr][3] += xv * w.w;
            }
        }
        #pragma unroll
        for (int rr = 0; rr < 8; rr++) {
            int r = rg * 8 + rr;
            if (r < rows) {
                float4 v4 = make_float4(acc[rr][0], acc[rr][1], acc[rr][2], acc[rr][3]);
                *(float4*)(C + (row0 + r) * 200 + cg * 4) = v4;
            }
        }
    }
}

// --------------------------- Attention per (i, h) --------------------------
// 128 threads, thread s = query row. K/V head slices in smem (broadcast reads).
// Score row lives in smem with pitch 129 (conflict-free). Per-thread softmax.
// Attention weights written via coalesced float4 staging pass.
__global__ __launch_bounds__(128, 2)
void attn128(const float* __restrict__ Q, const float* __restrict__ K,
             const float* __restrict__ V, float* __restrict__ AW,
             float* __restrict__ CTX) {
    extern __shared__ float sm[];
    float* ks   = sm;                       // 128*20
    float* vs   = sm + 2560;                // 128*20
    float* as   = sm + 5120;                // 128*129
    float* sinv = sm + 5120 + 128 * 129;    // 128

    const int i   = blockIdx.x;   // 0..1023
    const int h   = blockIdx.y;   // 0..9
    const int tid = threadIdx.x;  // query row s
    const long rb = (long)i * 128;
    const int hoff = h * 20;

    // Cooperative load of K,V head slices: 128 rows x 5 float4.
    {
        float4* ks4 = (float4*)ks;
        float4* vs4 = (float4*)vs;
        #pragma unroll
        for (int e0 = 0; e0 < 5; e0++) {
            int e = tid + e0 * 128;
            int r = e / 5, c = e - r * 5;
            const float* kp = K + (rb + r) * 200 + hoff + c * 4;
            const float* vp = V + (rb + r) * 200 + hoff + c * 4;
            ks4[e] = *(const float4*)kp;
            vs4[e] = *(const float4*)vp;
        }
    }
    // q row -> registers, fold in 1/sqrt(hd).
    float q[20];
    {
        const float* qp = Q + (rb + tid) * 200 + hoff;
        #pragma unroll
        for (int c = 0; c < 5; c++) {
            float4 t4 = *(const float4*)(qp + c * 4);
            q[c * 4 + 0] = t4.x; q[c * 4 + 1] = t4.y;
            q[c * 4 + 2] = t4.z; q[c * 4 + 3] = t4.w;
        }
        const float scale = 0.22360679774997896f;   // 1/sqrt(20)
        #pragma unroll
        for (int j = 0; j < 20; j++) q[j] *= scale;
    }
    __syncthreads();

    float* myrow = as + tid * 129;
    float mx = -1e30f;
    #pragma unroll 4
    for (int t = 0; t < 128; t++) {
        const float4* kt = (const float4*)(ks + t * 20);  // broadcast
        float acc = 0.f;
        #pragma unroll
        for (int c = 0; c < 5; c++) {
            float4 k4 = kt[c];
            acc += q[c * 4 + 0] * k4.x + q[c * 4 + 1] * k4.y
                 + q[c * 4 + 2] * k4.z + q[c * 4 + 3] * k4.w;
        }
        myrow[t] = acc;
        mx = fmaxf(mx, acc);
    }
    float ssum = 0.f;
    #pragma unroll 4
    for (int t = 0; t < 128; t++) {
        float e = __expf(myrow[t] - mx);
        myrow[t] = e;
        ssum += e;
    }
    const float inv = 1.0f / ssum;
    sinv[tid] = inv;

    // AV (normalize folded into the final store).
    float o[20];
    #pragma unroll
    for (int j = 0; j < 20; j++) o[j] = 0.f;
    #pragma unroll 2
    for (int t = 0; t < 128; t++) {
        float a = myrow[t];
        const float4* vt = (const float4*)(vs + t * 20);  // broadcast
        #pragma unroll
        for (int c = 0; c < 5; c++) {
            float4 v4 = vt[c];
            o[c * 4 + 0] += a * v4.x; o[c * 4 + 1] += a * v4.y;
            o[c * 4 + 2] += a * v4.z; o[c * 4 + 3] += a * v4.w;
        }
    }
    {
        float* cp = CTX + (rb + tid) * 200 + hoff;
        #pragma unroll
        for (int c = 0; c < 5; c++) {
            float4 v4 = make_float4(o[c * 4 + 0] * inv, o[c * 4 + 1] * inv,
                                    o[c * 4 + 2] * inv, o[c * 4 + 3] * inv);
            *(float4*)(cp + c * 4) = v4;
        }
    }
    __syncthreads();

    // Coalesced attention-weight store: 16384 floats = 4096 float4.
    {
        float4* awp = (float4*)(AW + (long)(i * 10 + h) * 16384);
        #pragma unroll
        for (int e0 = 0; e0 < 32; e0++) {
            int e = tid + e0 * 128;
            int s  = e >> 5;        // row
            int t4 = e & 31;        // float4 within row
            const float* src = as + s * 129 + t4 * 4;
            float iv = sinv[s];
            awp[e] = make_float4(src[0] * iv, src[1] * iv, src[2] * iv, src[3] * iv);
        }
    }
}

// ---------------------------------------------------------------------------
extern "C" void kernel_launch(void* const* d_in, const int* in_sizes, int n_in,
                              void* d_out, int out_size) {
    const float* x  = (const float*)d_in[0];
    const float* wq = (const float*)d_in[1];
    const float* wk = (const float*)d_in[2];
    const float* wv = (const float*)d_in[3];

    float* attn = (float*)d_out;                       // 1024*10*128*128
    float* out  = (float*)d_out + 167772160L;          // 131072*200

    float *gq, *gk, *gv, *gctx;
    cudaGetSymbolAddress((void**)&gq,   g_q);
    cudaGetSymbolAddress((void**)&gk,   g_k);
    cudaGetSymbolAddress((void**)&gv,   g_v);
    cudaGetSymbolAddress((void**)&gctx, g_ctx);

    const int SG_SMEM = (40000 + 80 * DPAD) * 4;                    // 224320 B
    const int AT_SMEM = (2560 + 2560 + 128 * 129 + 128) * 4;        //  87040 B
    cudaFuncSetAttribute(sgemm200, cudaFuncAttributeMaxDynamicSharedMemorySize, SG_SMEM);
    cudaFuncSetAttribute(attn128,  cudaFuncAttributeMaxDynamicSharedMemorySize, AT_SMEM);

    dim3 gg((131072 + 79) / 80);   // 1639 blocks

    sgemm200<<<gg, 512, SG_SMEM>>>(x, wq, gq);
    sgemm200<<<gg, 512, SG_SMEM>>>(x, wk, gk);
    sgemm200<<<gg, 512, SG_SMEM>>>(x, wv, gv);
    attn128<<<dim3(1024, 10), 128, AT_SMEM>>>(gq, gk, gv, attn, gctx);
    sgemm200<<<gg, 512, SG_SMEM>>>(gctx, wq, out);
}